// round 6
// baseline (speedup 1.0000x reference)
#include <cuda_runtime.h>

#define T_   100
#define R_   300
#define S_   500
#define P_   8
#define RC_  50
#define LOG2PI_ 1.8378770664093453f
#define DEATH_RATE_ 0.02f

#define BM 64
#define BN 64
#define BK 16
#define GT 128   // threads per GEMM block; micro tile 8x4 (i-packed f32x2)

#define NSLOTS 16384
#define SLOT_GEMM2  0      // 3960 blocks
#define SLOT_MISC   4096   // 3750 blocks
#define SLOT_STRAIN 8192   // 5000 blocks

// ---- scratch (device globals; no allocation allowed) ----
__device__ float  g_transitT[R_ * R_];                    // transitT[R][r] = transit[r][R]
__device__ float  g_mut[S_ * S_];                         // mut[s][S]
__device__ float  g_pred1[(size_t)(T_ - 1) * R_ * S_];    // 59.4 MB
__device__ double g_part[NSLOTS];

// packed f32x2 helpers (sm_103a) -------------------------------------------
__device__ __forceinline__ unsigned long long pack_dup_f32x2(float v) {
    unsigned long long d;
    unsigned int u = __float_as_uint(v);
    asm("mov.b64 %0, {%1, %1};" : "=l"(d) : "r"(u));
    return d;
}
__device__ __forceinline__ void fma_f32x2(unsigned long long& acc,
                                          unsigned long long a,
                                          unsigned long long b) {
    asm("fma.rn.f32x2 %0, %1, %2, %0;" : "+l"(acc) : "l"(a), "l"(b));
}

// ============================================================
__global__ void k_init() {
    int i = blockIdx.x * blockDim.x + threadIdx.x;
    if (i < NSLOTS) g_part[i] = 0.0;
}

__global__ void k_prep(const float* __restrict__ td, const float* __restrict__ tr,
                       const float* __restrict__ mm, const float* __restrict__ mrp) {
    int i = blockIdx.x * blockDim.x + threadIdx.x;
    if (i < R_ * R_) {
        int Rr = i / R_, r = i - Rr * R_;
        float a = 0.f;
#pragma unroll
        for (int p = 0; p < P_; p++)
            a += td[((size_t)r * R_ + Rr) * P_ + p] * tr[p];
        g_transitT[i] = a;   // = transit[r][Rr]
    }
    if (i < S_ * S_) {
        int s = i / S_, sn = i - s * S_;
        g_mut[i] = (s == sn ? 1.f : 0.f) + (*mrp) * mm[i];
    }
}

// ============================================================
// GEMM1: pred1[t,R,s] = sum_r transitT[R,r] * (inf[t,r,s]*R0*Rtr[t,r]*Rs[s])
__global__ __launch_bounds__(GT) void k_gemm1(const float* __restrict__ inf,
                                              const float* __restrict__ Rtr,
                                              const float* __restrict__ Rs,
                                              const float* __restrict__ R0p) {
    int t  = blockIdx.z;
    int m0 = blockIdx.y * BM;  // R index
    int n0 = blockIdx.x * BN;  // s index
    __shared__ __align__(16) float As[BK][BM + 4];
    __shared__ __align__(16) float Bs[BK][BN];
    int tid = threadIdx.x;
    int tx = tid & 15, ty = tid >> 4;
    unsigned long long acc2[4][4];   // [ipair][j]; each holds (i=2ip, i=2ip+1)
#pragma unroll
    for (int i = 0; i < 4; i++)
#pragma unroll
        for (int j = 0; j < 4; j++) acc2[i][j] = 0ULL;

    const float R0 = *R0p;
    const float* Bt   = inf + (size_t)t * R_ * S_;
    const float* RtrT = Rtr + t * R_;

    for (int k0 = 0; k0 < R_; k0 += BK) {
#pragma unroll
        for (int i = 0; i < (BM * BK) / GT; i++) {
            int idx = tid + i * GT;
            int k = idx & 15, m = idx >> 4;
            int gm = m0 + m, gk = k0 + k;
            As[k][m] = (gm < R_ && gk < R_) ? g_transitT[gm * R_ + gk] : 0.f;
        }
#pragma unroll
        for (int i = 0; i < (BK * BN) / GT; i++) {
            int idx = tid + i * GT;
            int n = idx & 63, k = idx >> 6;
            int gk = k0 + k, gn = n0 + n;
            float v = 0.f;
            if (gk < R_ && gn < S_)
                v = Bt[(size_t)gk * S_ + gn] * (R0 * RtrT[gk] * Rs[gn]);
            Bs[k][n] = v;
        }
        __syncthreads();
#pragma unroll
        for (int k = 0; k < BK; k++) {
            ulonglong2 ap0 = *(const ulonglong2*)&As[k][ty * 8];      // pairs (0,1),(2,3)
            ulonglong2 ap1 = *(const ulonglong2*)&As[k][ty * 8 + 4];  // pairs (4,5),(6,7)
            float4 b0 = *(const float4*)&Bs[k][tx * 4];
            unsigned long long ap[4] = {ap0.x, ap0.y, ap1.x, ap1.y};
            unsigned long long bb[4] = {pack_dup_f32x2(b0.x), pack_dup_f32x2(b0.y),
                                        pack_dup_f32x2(b0.z), pack_dup_f32x2(b0.w)};
#pragma unroll
            for (int ip = 0; ip < 4; ip++)
#pragma unroll
                for (int j = 0; j < 4; j++) fma_f32x2(acc2[ip][j], ap[ip], bb[j]);
        }
        __syncthreads();
    }

    float* C = g_pred1 + (size_t)t * R_ * S_;
#pragma unroll
    for (int ip = 0; ip < 4; ip++) {
#pragma unroll
        for (int j = 0; j < 4; j++) {
            float2 f = *(float2*)&acc2[ip][j];
            int gn = n0 + tx * 4 + j;
            int gm = m0 + ty * 8 + 2 * ip;
            if (gn < S_) {
                if (gm     < R_) C[(size_t)gm * S_ + gn]       = f.x;
                if (gm + 1 < R_) C[(size_t)(gm + 1) * S_ + gn] = f.y;
            }
        }
    }
}

// ============================================================
// GEMM2: pred[t,R,S] = sum_s pred1[t,R,s]*mut[s,S]; fused RelaxedPoisson LL epilogue
__global__ __launch_bounds__(GT) void k_gemm2(const float* __restrict__ inf,
                                              const float* __restrict__ iodp,
                                              int slotBase) {
    int t  = blockIdx.z;
    int m0 = blockIdx.y * BM;  // R index
    int n0 = blockIdx.x * BN;  // S index
    __shared__ __align__(16) float As[BK][BM + 4];
    __shared__ __align__(16) float Bs[BK][BN];
    __shared__ double red[GT];
    int tid = threadIdx.x;
    int tx = tid & 15, ty = tid >> 4;
    unsigned long long acc2[4][4];
#pragma unroll
    for (int i = 0; i < 4; i++)
#pragma unroll
        for (int j = 0; j < 4; j++) acc2[i][j] = 0ULL;

    const float* A = g_pred1 + (size_t)t * R_ * S_;

    for (int k0 = 0; k0 < S_; k0 += BK) {
#pragma unroll
        for (int i = 0; i < (BM * BK) / GT; i++) {
            int idx = tid + i * GT;
            int k = idx & 15, m = idx >> 4;
            int gm = m0 + m, gk = k0 + k;
            As[k][m] = (gm < R_ && gk < S_) ? A[(size_t)gm * S_ + gk] : 0.f;
        }
#pragma unroll
        for (int i = 0; i < (BK * BN) / GT; i++) {
            int idx = tid + i * GT;
            int n = idx & 63, k = idx >> 6;
            int gk = k0 + k, gn = n0 + n;
            Bs[k][n] = (gk < S_ && gn < S_) ? g_mut[gk * S_ + gn] : 0.f;
        }
        __syncthreads();
#pragma unroll
        for (int k = 0; k < BK; k++) {
            ulonglong2 ap0 = *(const ulonglong2*)&As[k][ty * 8];
            ulonglong2 ap1 = *(const ulonglong2*)&As[k][ty * 8 + 4];
            float4 b0 = *(const float4*)&Bs[k][tx * 4];
            unsigned long long ap[4] = {ap0.x, ap0.y, ap1.x, ap1.y};
            unsigned long long bb[4] = {pack_dup_f32x2(b0.x), pack_dup_f32x2(b0.y),
                                        pack_dup_f32x2(b0.z), pack_dup_f32x2(b0.w)};
#pragma unroll
            for (int ip = 0; ip < 4; ip++)
#pragma unroll
                for (int j = 0; j < 4; j++) fma_f32x2(acc2[ip][j], ap[ip], bb[j]);
        }
        __syncthreads();
    }

    // Epilogue: ll_step terms against infections[t+1]
    const float od = *iodp;
    const float* X = inf + (size_t)(t + 1) * R_ * S_;
    double lsum = 0.0;
#pragma unroll
    for (int ip = 0; ip < 4; ip++) {
#pragma unroll
        for (int j = 0; j < 4; j++) {
            float2 f = *(float2*)&acc2[ip][j];
            int gn = n0 + tx * 4 + j;
            if (gn >= S_) continue;
#pragma unroll
            for (int h = 0; h < 2; h++) {
                int gm = m0 + ty * 8 + 2 * ip + h;
                if (gm >= R_) continue;
                float p  = fmaxf(h ? f.y : f.x, 1e-3f);
                float s2 = log1pf(1.f / p + od);
                float mu = logf(p) - 0.5f * s2;
                float lx = logf(X[(size_t)gm * S_ + gn]);
                float d  = lx - mu;
                lsum += (double)(-lx - 0.5f * logf(s2) - 0.5f * LOG2PI_ - d * d / (2.f * s2));
            }
        }
    }
    red[tid] = lsum;
    __syncthreads();
#pragma unroll
    for (int o = GT / 2; o > 0; o >>= 1) {
        if (tid < o) red[tid] += red[tid + o];
        __syncthreads();
    }
    if (tid == 0) {
        int blin = (blockIdx.z * gridDim.y + blockIdx.y) * gridDim.x + blockIdx.x;
        g_part[slotBase + blin] = red[0];
    }
}

// ============================================================
__device__ __forceinline__ float negbin_lp(float k, float rate, float od) {
    // OverdispersedPoisson -> NB with r = 1/od, q = 1/(1+od*rate)
    float rnb = 1.f / od;
    float lq  = -logf(1.f + od * rate);
    float lp  = logf(od * rate) + lq;   // log(od*rate/(1+od*rate))
    return lgammaf(k + rnb) - lgammaf(rnb) - lgammaf(k + 1.f) + rnb * lq + k * lp;
}

// case + death negbin, Rtr drift. one warp per (t,r)
__global__ void k_misc(const float* __restrict__ inf, const float* __restrict__ crt,
                       const float* __restrict__ crr, const float* __restrict__ Rtr,
                       const float* __restrict__ caseD, const float* __restrict__ deathD,
                       const float* __restrict__ codp, const float* __restrict__ dodp,
                       const float* __restrict__ dsp, int slotBase) {
    __shared__ double red[256];
    int tid  = threadIdx.x;
    int w    = (blockIdx.x * blockDim.x + tid) >> 5;
    int lane = tid & 31;
    double lsum = 0.0;
    if (w < T_ * R_) {
        int t = w / R_, r = w - t * R_;
        const float* row = inf + (size_t)w * S_;
        float ssum = 0.f;
        for (int i = lane; i < S_; i += 32) ssum += row[i];
#pragma unroll
        for (int o = 16; o > 0; o >>= 1) ssum += __shfl_xor_sync(0xffffffffu, ssum, o);
        if (lane == 0) {
            lsum += (double)negbin_lp(caseD[w], ssum * crt[t] * crr[r], *codp);
            lsum += (double)negbin_lp(deathD[w], ssum * DEATH_RATE_, *dodp);
            if (t >= 1) {
                float ds = *dsp;
                float lx = logf(Rtr[w] / Rtr[w - R_]);
                lsum += (double)(-lx - logf(ds) - 0.5f * LOG2PI_ - lx * lx / (2.f * ds * ds));
            }
        }
    }
    red[tid] = lsum;
    __syncthreads();
#pragma unroll
    for (int o = 128; o > 0; o >>= 1) {
        if (tid < o) red[tid] += red[tid + o];
        __syncthreads();
    }
    if (tid == 0) g_part[slotBase + blockIdx.x] = red[0];
}

// ============================================================
__device__ __forceinline__ float blkred_f(float v, float* red, int tid) {
    red[tid] = v;
    __syncthreads();
#pragma unroll
    for (int o = 128; o > 0; o >>= 1) {
        if (tid < o) red[tid] += red[tid + o];
        __syncthreads();
    }
    float r = red[0];
    __syncthreads();
    return r;
}

// strain multinomial; one block per (t, coarse)
__global__ void k_strain(const float* __restrict__ inf, const float* __restrict__ strain,
                         const float* __restrict__ sampleM, int slotBase) {
    __shared__ float w[R_];
    __shared__ float red[256];
    int b = blockIdx.x;
    int t = b / RC_, c = b - t * RC_;
    int tid = threadIdx.x;
    for (int i = tid; i < R_; i += 256) w[i] = sampleM[c * R_ + i];
    __syncthreads();

    int s0 = tid, s1 = tid + 256;
    bool v1 = (s1 < S_);
    float c0 = 1e-6f, c1 = 1e-6f;
    const float* It = inf + (size_t)t * R_ * S_;
    for (int r = 0; r < R_; r++) {
        float wv = w[r];               // uniform across block
        if (wv != 0.f) {
            const float* rowp = It + (size_t)r * S_;
            c0 += wv * rowp[s0];
            if (v1) c1 += wv * rowp[s1];
        }
    }
    float total = blkred_f(c0 + (v1 ? c1 : 0.f), red, tid);

    const float* sd = strain + (size_t)b * S_;
    float sd0 = sd[s0], sd1 = v1 ? sd[s1] : 0.f;
    float lc0 = logf(c0);
    float lc1 = v1 ? logf(c1) : 0.f;

    float slc = blkred_f(sd0 * lc0 + sd1 * lc1, red, tid);
    float slg = blkred_f(lgammaf(sd0 + 1.f) + (v1 ? lgammaf(sd1 + 1.f) : 0.f), red, tid);
    float n   = blkred_f(sd0 + sd1, red, tid);

    if (tid == 0)
        g_part[slotBase + b] = (double)(lgammaf(n + 1.f) - slg + slc - n * logf(total));
}

// ============================================================
__global__ void k_final(float* __restrict__ out) {
    __shared__ double red[256];
    int tid = threadIdx.x;
    double s = 0.0;
    for (int i = tid; i < NSLOTS; i += 256) s += g_part[i];   // fixed order: deterministic
    red[tid] = s;
    __syncthreads();
#pragma unroll
    for (int o = 128; o > 0; o >>= 1) {
        if (tid < o) red[tid] += red[tid + o];
        __syncthreads();
    }
    if (tid == 0) out[0] = (float)red[0];
}

// ============================================================
extern "C" void kernel_launch(void* const* d_in, const int* in_sizes, int n_in,
                              void* d_out, int out_size) {
    const float* inf    = (const float*)d_in[0];
    const float* crt    = (const float*)d_in[1];
    const float* crr    = (const float*)d_in[2];
    const float* R0p    = (const float*)d_in[3];
    const float* Rs     = (const float*)d_in[4];
    const float* Rtr    = (const float*)d_in[5];
    const float* trate  = (const float*)d_in[6];
    const float* mrp    = (const float*)d_in[7];
    const float* iodp   = (const float*)d_in[8];
    const float* codp   = (const float*)d_in[9];
    const float* dodp   = (const float*)d_in[10];
    const float* dsp    = (const float*)d_in[11];
    const float* td     = (const float*)d_in[12];
    const float* caseD  = (const float*)d_in[13];
    const float* deathD = (const float*)d_in[14];
    const float* strain = (const float*)d_in[15];
    const float* sampM  = (const float*)d_in[16];
    const float* mm     = (const float*)d_in[17];
    float* out = (float*)d_out;

    k_init<<<(NSLOTS + 255) / 256, 256>>>();
    k_prep<<<(S_ * S_ + 255) / 256, 256>>>(td, trate, mm, mrp);

    dim3 gg((S_ + BN - 1) / BN, (R_ + BM - 1) / BM, T_ - 1);   // (8, 5, 99)
    k_gemm1<<<gg, GT>>>(inf, Rtr, Rs, R0p);
    k_gemm2<<<gg, GT>>>(inf, iodp, SLOT_GEMM2);

    k_misc<<<(T_ * R_ * 32 + 255) / 256, 256>>>(inf, crt, crr, Rtr, caseD, deathD,
                                                codp, dodp, dsp, SLOT_MISC);
    k_strain<<<T_ * RC_, 256>>>(inf, strain, sampM, SLOT_STRAIN);
    k_final<<<1, 256>>>(out);
}

// round 8
// speedup vs baseline: 1.1190x; 1.1190x over previous
#include <cuda_runtime.h>

#define T_   100
#define R_   300
#define S_   500
#define P_   8
#define RC_  50
#define LOG2PI_ 1.8378770664093453f
#define DEATH_RATE_ 0.02f

#define BM 64
#define BN 64
#define BK 16
#define GT 128   // threads per GEMM block; micro tile 8x4 (i-packed f32x2)

#define NSLOTS 16384
#define SLOT_GEMM2  0      // 3960 blocks
#define SLOT_MISC   4096   // 3750 blocks
#define SLOT_STRAIN 8192   // 5000 blocks

// ---- scratch (device globals; no allocation allowed) ----
__device__ float  g_transitT[R_ * R_];                    // transitT[R][r] = transit[r][R]
__device__ float  g_mut[S_ * S_];                         // mut[s][S]
__device__ float  g_pred1[(size_t)(T_ - 1) * R_ * S_];    // 59.4 MB
__device__ double g_part[NSLOTS];

// packed f32x2 helpers (sm_103a) -------------------------------------------
__device__ __forceinline__ unsigned long long pack_dup_f32x2(float v) {
    unsigned long long d;
    unsigned int u = __float_as_uint(v);
    asm("mov.b64 %0, {%1, %1};" : "=l"(d) : "r"(u));
    return d;
}
__device__ __forceinline__ void fma_f32x2(unsigned long long& acc,
                                          unsigned long long a,
                                          unsigned long long b) {
    asm("fma.rn.f32x2 %0, %1, %2, %0;" : "+l"(acc) : "l"(a), "l"(b));
}

// ============================================================
__global__ void k_init() {
    int i = blockIdx.x * blockDim.x + threadIdx.x;
    if (i < NSLOTS) g_part[i] = 0.0;
}

__global__ void k_prep(const float* __restrict__ td, const float* __restrict__ tr,
                       const float* __restrict__ mm, const float* __restrict__ mrp) {
    int i = blockIdx.x * blockDim.x + threadIdx.x;
    if (i < R_ * R_) {
        int Rr = i / R_, r = i - Rr * R_;
        float a = 0.f;
#pragma unroll
        for (int p = 0; p < P_; p++)
            a += td[((size_t)r * R_ + Rr) * P_ + p] * tr[p];
        g_transitT[i] = a;   // = transit[r][Rr]
    }
    if (i < S_ * S_) {
        int s = i / S_, sn = i - s * S_;
        g_mut[i] = (s == sn ? 1.f : 0.f) + (*mrp) * mm[i];
    }
}

// ============================================================
// Shared compute step on one smem tile (8x4 micro-tile, i-packed f32x2)
__device__ __forceinline__ void mm_tile(const float (*As)[BM + 4], const float (*Bs)[BN],
                                        int tx, int ty, unsigned long long acc2[4][4]) {
#pragma unroll
    for (int k = 0; k < BK; k++) {
        ulonglong2 ap0 = *(const ulonglong2*)&As[k][ty * 8];      // pairs (0,1),(2,3)
        ulonglong2 ap1 = *(const ulonglong2*)&As[k][ty * 8 + 4];  // pairs (4,5),(6,7)
        float4 b0 = *(const float4*)&Bs[k][tx * 4];
        unsigned long long ap[4] = {ap0.x, ap0.y, ap1.x, ap1.y};
        unsigned long long bb[4] = {pack_dup_f32x2(b0.x), pack_dup_f32x2(b0.y),
                                    pack_dup_f32x2(b0.z), pack_dup_f32x2(b0.w)};
#pragma unroll
        for (int ip = 0; ip < 4; ip++)
#pragma unroll
            for (int j = 0; j < 4; j++) fma_f32x2(acc2[ip][j], ap[ip], bb[j]);
    }
}

// ============================================================
// GEMM1: pred1[t,R,s] = sum_r transitT[R,r] * (inf[t,r,s]*R0*Rtr[t,r]*Rs[s])
// double-buffered smem pipeline, one __syncthreads per K-tile
__global__ __launch_bounds__(GT) void k_gemm1(const float* __restrict__ inf,
                                              const float* __restrict__ Rtr,
                                              const float* __restrict__ Rs,
                                              const float* __restrict__ R0p) {
    int t  = blockIdx.z;
    int m0 = blockIdx.y * BM;  // R index
    int n0 = blockIdx.x * BN;  // s index
    __shared__ __align__(16) float As[2][BK][BM + 4];
    __shared__ __align__(16) float Bs[2][BK][BN];
    int tid = threadIdx.x;
    int tx = tid & 15, ty = tid >> 4;
    unsigned long long acc2[4][4];
#pragma unroll
    for (int i = 0; i < 4; i++)
#pragma unroll
        for (int j = 0; j < 4; j++) acc2[i][j] = 0ULL;

    const float R0 = *R0p;
    const float* Bt   = inf + (size_t)t * R_ * S_;
    const float* RtrT = Rtr + t * R_;

    // per-thread load coords (invariant across tiles)
    // As tile is BK x BM = 16 x 64: lkA in 0..15, lmA in 0..7, m strides by 8
    const int lkA = tid & 15, lmA = tid >> 4;
    // Bs tile is BK x BN = 16 x 64: lnB in 0..63, lkB in 0..1, k strides by 2
    const int lnB = tid & 63, lkB = tid >> 6;

    float ra[8], rb[8];
    // ---- load tile 0 ----
#pragma unroll
    for (int i = 0; i < 8; i++) {
        int gm = m0 + lmA + i * 8, gk = lkA;
        As[0][lkA][lmA + i * 8] = (gm < R_ && gk < R_) ? g_transitT[gm * R_ + gk] : 0.f;
    }
#pragma unroll
    for (int i = 0; i < 8; i++) {
        int gk = lkB + i * 2, gn = n0 + lnB;
        float v = 0.f;
        if (gk < R_ && gn < S_)
            v = Bt[(size_t)gk * S_ + gn] * (R0 * RtrT[gk] * Rs[gn]);
        Bs[0][lkB + i * 2][lnB] = v;
    }
    __syncthreads();

    const int NT = (R_ + BK - 1) / BK;   // 19
    for (int it = 0; it < NT; it++) {
        int buf = it & 1;
        bool has = (it + 1) < NT;
        if (has) {
            int kb = (it + 1) * BK;
#pragma unroll
            for (int i = 0; i < 8; i++) {
                int gm = m0 + lmA + i * 8, gk = kb + lkA;
                ra[i] = (gm < R_ && gk < R_) ? g_transitT[gm * R_ + gk] : 0.f;
            }
#pragma unroll
            for (int i = 0; i < 8; i++) {
                int gk = kb + lkB + i * 2, gn = n0 + lnB;
                float v = 0.f;
                if (gk < R_ && gn < S_)
                    v = Bt[(size_t)gk * S_ + gn] * (R0 * RtrT[gk] * Rs[gn]);
                rb[i] = v;
            }
        }
        mm_tile(As[buf], Bs[buf], tx, ty, acc2);
        if (has) {
#pragma unroll
            for (int i = 0; i < 8; i++) As[buf ^ 1][lkA][lmA + i * 8] = ra[i];
#pragma unroll
            for (int i = 0; i < 8; i++) Bs[buf ^ 1][lkB + i * 2][lnB] = rb[i];
            __syncthreads();
        }
    }

    float* C = g_pred1 + (size_t)t * R_ * S_;
#pragma unroll
    for (int ip = 0; ip < 4; ip++) {
#pragma unroll
        for (int j = 0; j < 4; j++) {
            float2 f = *(float2*)&acc2[ip][j];
            int gn = n0 + tx * 4 + j;
            int gm = m0 + ty * 8 + 2 * ip;
            if (gn < S_) {
                if (gm     < R_) C[(size_t)gm * S_ + gn]       = f.x;
                if (gm + 1 < R_) C[(size_t)(gm + 1) * S_ + gn] = f.y;
            }
        }
    }
}

// ============================================================
// GEMM2: pred[t,R,S] = sum_s pred1[t,R,s]*mut[s,S]; fused RelaxedPoisson LL epilogue
__global__ __launch_bounds__(GT) void k_gemm2(const float* __restrict__ inf,
                                              const float* __restrict__ iodp,
                                              int slotBase) {
    int t  = blockIdx.z;
    int m0 = blockIdx.y * BM;  // R index
    int n0 = blockIdx.x * BN;  // S index
    __shared__ __align__(16) float As[2][BK][BM + 4];
    __shared__ __align__(16) float Bs[2][BK][BN];
    __shared__ double red[GT];
    int tid = threadIdx.x;
    int tx = tid & 15, ty = tid >> 4;
    unsigned long long acc2[4][4];
#pragma unroll
    for (int i = 0; i < 4; i++)
#pragma unroll
        for (int j = 0; j < 4; j++) acc2[i][j] = 0ULL;

    const float* A = g_pred1 + (size_t)t * R_ * S_;

    const int lkA = tid & 15, lmA = tid >> 4;   // m strides by 8
    const int lnB = tid & 63, lkB = tid >> 6;   // k strides by 2

    float ra[8], rb[8];
    // ---- load tile 0 ----
#pragma unroll
    for (int i = 0; i < 8; i++) {
        int gm = m0 + lmA + i * 8, gk = lkA;
        As[0][lkA][lmA + i * 8] = (gm < R_ && gk < S_) ? A[(size_t)gm * S_ + gk] : 0.f;
    }
#pragma unroll
    for (int i = 0; i < 8; i++) {
        int gk = lkB + i * 2, gn = n0 + lnB;
        Bs[0][lkB + i * 2][lnB] = (gk < S_ && gn < S_) ? g_mut[gk * S_ + gn] : 0.f;
    }
    __syncthreads();

    const int NT = (S_ + BK - 1) / BK;   // 32
    for (int it = 0; it < NT; it++) {
        int buf = it & 1;
        bool has = (it + 1) < NT;
        if (has) {
            int kb = (it + 1) * BK;
#pragma unroll
            for (int i = 0; i < 8; i++) {
                int gm = m0 + lmA + i * 8, gk = kb + lkA;
                ra[i] = (gm < R_ && gk < S_) ? A[(size_t)gm * S_ + gk] : 0.f;
            }
#pragma unroll
            for (int i = 0; i < 8; i++) {
                int gk = kb + lkB + i * 2, gn = n0 + lnB;
                rb[i] = (gk < S_ && gn < S_) ? g_mut[gk * S_ + gn] : 0.f;
            }
        }
        mm_tile(As[buf], Bs[buf], tx, ty, acc2);
        if (has) {
#pragma unroll
            for (int i = 0; i < 8; i++) As[buf ^ 1][lkA][lmA + i * 8] = ra[i];
#pragma unroll
            for (int i = 0; i < 8; i++) Bs[buf ^ 1][lkB + i * 2][lnB] = rb[i];
            __syncthreads();
        }
    }

    // Epilogue: ll_step terms against infections[t+1]
    const float od = *iodp;
    const float* X = inf + (size_t)(t + 1) * R_ * S_;
    double lsum = 0.0;
#pragma unroll
    for (int ip = 0; ip < 4; ip++) {
#pragma unroll
        for (int j = 0; j < 4; j++) {
            float2 f = *(float2*)&acc2[ip][j];
            int gn = n0 + tx * 4 + j;
            if (gn >= S_) continue;
#pragma unroll
            for (int h = 0; h < 2; h++) {
                int gm = m0 + ty * 8 + 2 * ip + h;
                if (gm >= R_) continue;
                float p  = fmaxf(h ? f.y : f.x, 1e-3f);
                float s2 = log1pf(1.f / p + od);
                float mu = logf(p) - 0.5f * s2;
                float lx = logf(X[(size_t)gm * S_ + gn]);
                float d  = lx - mu;
                lsum += (double)(-lx - 0.5f * logf(s2) - 0.5f * LOG2PI_ - d * d / (2.f * s2));
            }
        }
    }
    red[tid] = lsum;
    __syncthreads();
#pragma unroll
    for (int o = GT / 2; o > 0; o >>= 1) {
        if (tid < o) red[tid] += red[tid + o];
        __syncthreads();
    }
    if (tid == 0) {
        int blin = (blockIdx.z * gridDim.y + blockIdx.y) * gridDim.x + blockIdx.x;
        g_part[slotBase + blin] = red[0];
    }
}

// ============================================================
__device__ __forceinline__ float negbin_lp(float k, float rate, float od) {
    // OverdispersedPoisson -> NB with r = 1/od, q = 1/(1+od*rate)
    float rnb = 1.f / od;
    float lq  = -logf(1.f + od * rate);
    float lp  = logf(od * rate) + lq;   // log(od*rate/(1+od*rate))
    return lgammaf(k + rnb) - lgammaf(rnb) - lgammaf(k + 1.f) + rnb * lq + k * lp;
}

// case + death negbin, Rtr drift. one warp per (t,r)
__global__ void k_misc(const float* __restrict__ inf, const float* __restrict__ crt,
                       const float* __restrict__ crr, const float* __restrict__ Rtr,
                       const float* __restrict__ caseD, const float* __restrict__ deathD,
                       const float* __restrict__ codp, const float* __restrict__ dodp,
                       const float* __restrict__ dsp, int slotBase) {
    __shared__ double red[256];
    int tid  = threadIdx.x;
    int w    = (blockIdx.x * blockDim.x + tid) >> 5;
    int lane = tid & 31;
    double lsum = 0.0;
    if (w < T_ * R_) {
        int t = w / R_, r = w - t * R_;
        const float* row = inf + (size_t)w * S_;
        float ssum = 0.f;
        for (int i = lane; i < S_; i += 32) ssum += row[i];
#pragma unroll
        for (int o = 16; o > 0; o >>= 1) ssum += __shfl_xor_sync(0xffffffffu, ssum, o);
        if (lane == 0) {
            lsum += (double)negbin_lp(caseD[w], ssum * crt[t] * crr[r], *codp);
            lsum += (double)negbin_lp(deathD[w], ssum * DEATH_RATE_, *dodp);
            if (t >= 1) {
                float ds = *dsp;
                float lx = logf(Rtr[w] / Rtr[w - R_]);
                lsum += (double)(-lx - logf(ds) - 0.5f * LOG2PI_ - lx * lx / (2.f * ds * ds));
            }
        }
    }
    red[tid] = lsum;
    __syncthreads();
#pragma unroll
    for (int o = 128; o > 0; o >>= 1) {
        if (tid < o) red[tid] += red[tid + o];
        __syncthreads();
    }
    if (tid == 0) g_part[slotBase + blockIdx.x] = red[0];
}

// ============================================================
__device__ __forceinline__ float blkred_f(float v, float* red, int tid) {
    red[tid] = v;
    __syncthreads();
#pragma unroll
    for (int o = 128; o > 0; o >>= 1) {
        if (tid < o) red[tid] += red[tid + o];
        __syncthreads();
    }
    float r = red[0];
    __syncthreads();
    return r;
}

// strain multinomial; one block per (t, coarse)
__global__ void k_strain(const float* __restrict__ inf, const float* __restrict__ strain,
                         const float* __restrict__ sampleM, int slotBase) {
    __shared__ float w[R_];
    __shared__ float red[256];
    int b = blockIdx.x;
    int t = b / RC_, c = b - t * RC_;
    int tid = threadIdx.x;
    for (int i = tid; i < R_; i += 256) w[i] = sampleM[c * R_ + i];
    __syncthreads();

    int s0 = tid, s1 = tid + 256;
    bool v1 = (s1 < S_);
    float c0 = 1e-6f, c1 = 1e-6f;
    const float* It = inf + (size_t)t * R_ * S_;
    for (int r = 0; r < R_; r++) {
        float wv = w[r];               // uniform across block
        if (wv != 0.f) {
            const float* rowp = It + (size_t)r * S_;
            c0 += wv * rowp[s0];
            if (v1) c1 += wv * rowp[s1];
        }
    }
    float total = blkred_f(c0 + (v1 ? c1 : 0.f), red, tid);

    const float* sd = strain + (size_t)b * S_;
    float sd0 = sd[s0], sd1 = v1 ? sd[s1] : 0.f;
    float lc0 = logf(c0);
    float lc1 = v1 ? logf(c1) : 0.f;

    float slc = blkred_f(sd0 * lc0 + sd1 * lc1, red, tid);
    float slg = blkred_f(lgammaf(sd0 + 1.f) + (v1 ? lgammaf(sd1 + 1.f) : 0.f), red, tid);
    float n   = blkred_f(sd0 + sd1, red, tid);

    if (tid == 0)
        g_part[slotBase + b] = (double)(lgammaf(n + 1.f) - slg + slc - n * logf(total));
}

// ============================================================
__global__ void k_final(float* __restrict__ out) {
    __shared__ double red[256];
    int tid = threadIdx.x;
    double s = 0.0;
    for (int i = tid; i < NSLOTS; i += 256) s += g_part[i];   // fixed order: deterministic
    red[tid] = s;
    __syncthreads();
#pragma unroll
    for (int o = 128; o > 0; o >>= 1) {
        if (tid < o) red[tid] += red[tid + o];
        __syncthreads();
    }
    if (tid == 0) out[0] = (float)red[0];
}

// ============================================================
extern "C" void kernel_launch(void* const* d_in, const int* in_sizes, int n_in,
                              void* d_out, int out_size) {
    const float* inf    = (const float*)d_in[0];
    const float* crt    = (const float*)d_in[1];
    const float* crr    = (const float*)d_in[2];
    const float* R0p    = (const float*)d_in[3];
    const float* Rs     = (const float*)d_in[4];
    const float* Rtr    = (const float*)d_in[5];
    const float* trate  = (const float*)d_in[6];
    const float* mrp    = (const float*)d_in[7];
    const float* iodp   = (const float*)d_in[8];
    const float* codp   = (const float*)d_in[9];
    const float* dodp   = (const float*)d_in[10];
    const float* dsp    = (const float*)d_in[11];
    const float* td     = (const float*)d_in[12];
    const float* caseD  = (const float*)d_in[13];
    const float* deathD = (const float*)d_in[14];
    const float* strain = (const float*)d_in[15];
    const float* sampM  = (const float*)d_in[16];
    const float* mm     = (const float*)d_in[17];
    float* out = (float*)d_out;

    k_init<<<(NSLOTS + 255) / 256, 256>>>();
    k_prep<<<(S_ * S_ + 255) / 256, 256>>>(td, trate, mm, mrp);

    dim3 gg((S_ + BN - 1) / BN, (R_ + BM - 1) / BM, T_ - 1);   // (8, 5, 99)
    k_gemm1<<<gg, GT>>>(inf, Rtr, Rs, R0p);
    k_gemm2<<<gg, GT>>>(inf, iodp, SLOT_GEMM2);

    k_misc<<<(T_ * R_ * 32 + 255) / 256, 256>>>(inf, crt, crr, Rtr, caseD, deathD,
                                                codp, dodp, dsp, SLOT_MISC);
    k_strain<<<T_ * RC_, 256>>>(inf, strain, sampM, SLOT_STRAIN);
    k_final<<<1, 256>>>(out);
}